// round 16
// baseline (speedup 1.0000x reference)
#include <cuda_runtime.h>
#include <cuda_fp16.h>
#include <cstdint>
#include <math.h>

// ---------------------------------------------------------------------------
// ParallelTransformerBlock, fp16 tensor-core path (mma.sync m16n8k16 + ldmatrix
// + cp.async). fp32 accumulate everywhere.
// R16: flash-attention Q-tile 128 (256 thr, KV traffic halved, 256 CTAs);
//      merged single weight-convert launch. GEMMs identical to R15.
// ---------------------------------------------------------------------------

#define NSEQ 2048
#define DIM 2048
#define DH 128
#define HEADS 16
#define ATTN_INNER 2048
#define FF_INNER 8192
#define FUSED_OUT 18688
#define FF_BASE 2304      // ATTN_INNER + 2*DH
#define GATE_BASE 10496   // FF_BASE + FF_INNER
#define CAT_K (ATTN_INNER + FF_INNER)   // 10240
#define LN_EPS 1e-5f

// ------------------------- device scratch (static) -------------------------
__device__ __half g_xnh[(size_t)NSEQ * DIM];                    // 8 MB
__device__ __half g_projh[(size_t)NSEQ * FUSED_OUT];            // 76.5 MB
__device__ __half g_cath[(size_t)NSEQ * CAT_K];                 // 40 MB
__device__ __half g_wfh[(size_t)DIM * FUSED_OUT];               // 76.5 MB  [K][N]
__device__ __half g_wcath[(size_t)CAT_K * DIM];                 // 40 MB    [10240][2048]

// --------------------------- PTX helpers -----------------------------------
__device__ __forceinline__ uint32_t smem_u32(const void* p) {
    uint32_t a;
    asm("{ .reg .u64 t; cvta.to.shared.u64 t, %1; cvt.u32.u64 %0, t; }"
        : "=r"(a) : "l"(p));
    return a;
}

__device__ __forceinline__ uint32_t h2_u32(__half2 h) {
    union { __half2 h; uint32_t u; } cvt;
    cvt.h = h;
    return cvt.u;
}

#define CP_ASYNC16(smaddr, gptr) \
    asm volatile("cp.async.cg.shared.global [%0], [%1], 16;" :: "r"(smaddr), "l"(gptr))
#define CP_COMMIT() asm volatile("cp.async.commit_group;" ::: "memory")
#define CP_WAIT0()  asm volatile("cp.async.wait_group 0;" ::: "memory")
#define CP_WAIT1()  asm volatile("cp.async.wait_group 1;" ::: "memory")
#define CP_WAIT2()  asm volatile("cp.async.wait_group 2;" ::: "memory")

#define LDSM4(r, addr) \
    asm volatile("ldmatrix.sync.aligned.m8n8.x4.shared.b16 {%0,%1,%2,%3}, [%4];" \
                 : "=r"((r)[0]), "=r"((r)[1]), "=r"((r)[2]), "=r"((r)[3]) \
                 : "r"(addr))

#define LDSM4T(r, addr) \
    asm volatile("ldmatrix.sync.aligned.m8n8.x4.trans.shared.b16 {%0,%1,%2,%3}, [%4];" \
                 : "=r"((r)[0]), "=r"((r)[1]), "=r"((r)[2]), "=r"((r)[3]) \
                 : "r"(addr))

__device__ __forceinline__ void mma16816(float* d, const uint32_t* a, const uint32_t* b) {
    asm volatile(
        "mma.sync.aligned.m16n8k16.row.col.f32.f16.f16.f32 "
        "{%0,%1,%2,%3}, {%4,%5,%6,%7}, {%8,%9}, {%0,%1,%2,%3};"
        : "+f"(d[0]), "+f"(d[1]), "+f"(d[2]), "+f"(d[3])
        : "r"(a[0]), "r"(a[1]), "r"(a[2]), "r"(a[3]), "r"(b[0]), "r"(b[1]));
}

// ------------------------------ LayerNorm ----------------------------------
__global__ __launch_bounds__(256) void ln_kernel(const float* __restrict__ x,
                                                 const float* __restrict__ gamma) {
    int row = blockIdx.x;
    int tid = threadIdx.x;
    const float4* xr = (const float4*)(x + (size_t)row * DIM);
    __half2* out = (__half2*)(g_xnh + (size_t)row * DIM);
    const float4* g4 = (const float4*)gamma;

    float s = 0.f, sq = 0.f;
    float4 v[2];
    #pragma unroll
    for (int i = 0; i < 2; i++) {
        v[i] = xr[tid + 256 * i];
        s += v[i].x + v[i].y + v[i].z + v[i].w;
        sq += v[i].x * v[i].x + v[i].y * v[i].y + v[i].z * v[i].z + v[i].w * v[i].w;
    }
    __shared__ float red[256], red2[256];
    red[tid] = s; red2[tid] = sq;
    __syncthreads();
    for (int off = 128; off > 0; off >>= 1) {
        if (tid < off) { red[tid] += red[tid + off]; red2[tid] += red2[tid + off]; }
        __syncthreads();
    }
    float mu = red[0] * (1.0f / DIM);
    float var = red2[0] * (1.0f / DIM) - mu * mu;
    float inv = rsqrtf(var + LN_EPS);
    #pragma unroll
    for (int i = 0; i < 2; i++) {
        float4 g = g4[tid + 256 * i];
        float a0 = (v[i].x - mu) * inv * g.x;
        float a1 = (v[i].y - mu) * inv * g.y;
        float a2 = (v[i].z - mu) * inv * g.z;
        float a3 = (v[i].w - mu) * inv * g.w;
        out[(tid + 256 * i) * 2 + 0] = __floats2half2_rn(a0, a1);
        out[(tid + 256 * i) * 2 + 1] = __floats2half2_rn(a2, a3);
    }
}

// ----------------- weight fp32 -> fp16 streaming convert --------------------
// Single launch; blockIdx.y selects which tensor. Pure layout-preserving copy.
__global__ __launch_bounds__(256) void wconv3_kernel(
    const float* __restrict__ s0, __half* __restrict__ d0, size_t n0,
    const float* __restrict__ s1, __half* __restrict__ d1, size_t n1,
    const float* __restrict__ s2, __half* __restrict__ d2, size_t n2) {
    const float* src; __half* dst; size_t n;
    if (blockIdx.y == 0)      { src = s0; dst = d0; n = n0; }
    else if (blockIdx.y == 1) { src = s1; dst = d1; n = n1; }
    else                      { src = s2; dst = d2; n = n2; }
    size_t stride = (size_t)gridDim.x * 256 * 8;
    for (size_t i = ((size_t)blockIdx.x * 256 + threadIdx.x) * 8; i < n; i += stride) {
        float4 a = *(const float4*)(src + i);
        float4 b = *(const float4*)(src + i + 4);
        uint4 o;
        o.x = h2_u32(__floats2half2_rn(a.x, a.y));
        o.y = h2_u32(__floats2half2_rn(a.z, a.w));
        o.z = h2_u32(__floats2half2_rn(b.x, b.y));
        o.w = h2_u32(__floats2half2_rn(b.z, b.w));
        *(uint4*)(dst + i) = o;
    }
}

// ------------------------- fp16 tensor-core GEMM ----------------------------
// C[M,N] = A[M,K] @ B, A half [M][K] k-contig, B half [K][N] n-contig
// (consumed via ldmatrix.trans). 256x128x64 CTA tile, 4-stage cp.async,
// 256 threads: 8 warps 4(m) x 2(n), each warp 64x64.
#define ROWB   144                      // A smem row: 64 halves + 8 pad
#define BROWB  272                      // B smem row: 128 halves + 8 pad
#define ABYTES (256 * ROWB)             // 36864
#define BBYTES (64 * BROWB)             // 17408
#define STAGE  (ABYTES + BBYTES)        // 54272
#define NSTG   4

template <bool CHALF>
__global__ __launch_bounds__(256, 1)
void mma_gemm(const __half* __restrict__ A, long long lda,
              const __half* __restrict__ B, long long ldb,
              void* __restrict__ Cv, long long ldc,
              int K)
{
    const int bx = blockIdx.x;   // m tile
    const int by = blockIdx.y;   // n tile

    const int m0 = bx * 256;
    const int n0 = by * 128;
    const int NT = K >> 6;

    extern __shared__ char smem[];
    const uint32_t sm_u = smem_u32(smem);

    const int tid = threadIdx.x;
    const int lane = tid & 31;
    const int warp = tid >> 5;
    const int wm = warp & 3;
    const int wn = warp >> 2;
    const int g = lane >> 2;
    const int tig = lane & 3;

    const uint32_t a_off = (uint32_t)((wm * 64 + (lane & 15)) * ROWB + ((lane >> 4) << 4));
    const uint32_t b_off = (uint32_t)(ABYTES +
        (lane & 15) * BROWB + wn * 128 + ((lane >> 4) << 4));

    float acc[4][8][4];
    #pragma unroll
    for (int i = 0; i < 4; i++)
        #pragma unroll
        for (int j = 0; j < 8; j++)
            #pragma unroll
            for (int r = 0; r < 4; r++) acc[i][j][r] = 0.f;

    auto load_stage = [&](int st, int t) {
        const uint32_t abase = sm_u + st * STAGE;
        const uint32_t bbase = abase + ABYTES;
        const long long kk = (long long)t << 6;
        #pragma unroll
        for (int i = 0; i < 8; i++) {              // A: 256 rows x 128B
            int idx = tid + 256 * i;
            int row = idx >> 3, seg = idx & 7;
            uint32_t so = abase + (uint32_t)(row * ROWB + seg * 16);
            const __half* gp = A + (size_t)(m0 + row) * lda + kk + seg * 8;
            CP_ASYNC16(so, gp);
        }
        #pragma unroll
        for (int i = 0; i < 4; i++) {              // B: 64 k-rows x 256B
            int idx = tid + 256 * i;
            int row = idx >> 4, seg = idx & 15;
            uint32_t so = bbase + (uint32_t)(row * BROWB + seg * 16);
            const __half* gp = B + (size_t)(kk + row) * ldb + n0 + seg * 8;
            CP_ASYNC16(so, gp);
        }
    };

    #pragma unroll
    for (int s = 0; s < NSTG - 1; s++) {
        if (s < NT) load_stage(s, s);
        CP_COMMIT();
    }
    CP_WAIT2();
    __syncthreads();

    int st = 0;
    for (int t = 0; t < NT; t++) {
        int lt = t + NSTG - 1;
        int lst = st + NSTG - 1; if (lst >= NSTG) lst -= NSTG;
        if (lt < NT) load_stage(lst, lt);
        CP_COMMIT();

        const uint32_t abase = sm_u + st * STAGE;

        #pragma unroll
        for (int ks = 0; ks < 4; ks++) {
            uint32_t af[4][4], bf[4][4];
            #pragma unroll
            for (int mi = 0; mi < 4; mi++)
                LDSM4(af[mi], abase + a_off + mi * (16 * ROWB) + ks * 32);
            #pragma unroll
            for (int njp = 0; njp < 4; njp++)
                LDSM4T(bf[njp], abase + b_off + njp * 32 + ks * (16 * BROWB));
            #pragma unroll
            for (int mi = 0; mi < 4; mi++)
                #pragma unroll
                for (int njp = 0; njp < 4; njp++) {
                    mma16816(acc[mi][2 * njp + 0], af[mi], &bf[njp][0]);
                    mma16816(acc[mi][2 * njp + 1], af[mi], &bf[njp][2]);
                }
        }
        CP_WAIT2();
        __syncthreads();
        if (++st == NSTG) st = 0;
    }

    #pragma unroll
    for (int mi = 0; mi < 4; mi++) {
        #pragma unroll
        for (int nj = 0; nj < 8; nj++) {
            int row = m0 + wm * 64 + mi * 16 + g;
            int col = n0 + wn * 64 + nj * 8 + tig * 2;
            if (CHALF) {
                __half* C = (__half*)Cv;
                *(__half2*)(C + (size_t)row * ldc + col) =
                    __floats2half2_rn(acc[mi][nj][0], acc[mi][nj][1]);
                *(__half2*)(C + (size_t)(row + 8) * ldc + col) =
                    __floats2half2_rn(acc[mi][nj][2], acc[mi][nj][3]);
            } else {
                float* C = (float*)Cv;
                *(float2*)(C + (size_t)row * ldc + col) =
                    make_float2(acc[mi][nj][0], acc[mi][nj][1]);
                *(float2*)(C + (size_t)(row + 8) * ldc + col) =
                    make_float2(acc[mi][nj][2], acc[mi][nj][3]);
            }
        }
    }
}

// ------------------------- fused flash attention -----------------------------
// grid (16 qblocks x 16 heads), 256 threads (8 warps, 16 q-rows each => 128
// q-rows per CTA). KV loaded once per 128 q-rows (half the traffic of R15).
// K: [seq][dh] k-contig (non-trans ldmatrix); V: [seq][dh] (trans ldmatrix).
#define FQ_ROWB 272                     // 128 halves + 8 pad
#define FQ_BYTES (128 * FQ_ROWB)        // 34816
#define FK_BYTES (64 * FQ_ROWB)         // 17408
#define FV_BYTES (64 * FQ_ROWB)         // 17408
#define FSTAGE   (FK_BYTES + FV_BYTES)  // 34816
#define FSMEM    (FQ_BYTES + 2 * FSTAGE)// 104448

__global__ __launch_bounds__(256, 1)
void flash_attn(void) {
    const int qb = gridDim.x - 1 - blockIdx.x;      // big workloads first
    const int h = blockIdx.y;
    const int q0 = qb * 128;
    const int jmax = 2 * qb + 1;                    // 64-wide k-blocks 0..jmax

    extern __shared__ char smem[];
    const uint32_t sm_u = smem_u32(smem);
    const uint32_t kbase0 = sm_u + FQ_BYTES;

    const int tid = threadIdx.x;
    const int lane = tid & 31;
    const int w = tid >> 5;                          // 0..7

    const __half* Qg = g_projh + (size_t)h * DH;     // row stride FUSED_OUT
    const __half* Kg = g_projh + ATTN_INNER;
    const __half* Vg = g_projh + ATTN_INNER + DH;

    // ---- load + pre-scale Q into smem (128 rows) ----
    {
        const float scale = 0.08838834764831845f;
        for (int i = tid; i < 128 * 64; i += 256) {  // half2 granularity
            int row = i >> 6, c2 = i & 63;
            __half2 qv = *(const __half2*)(Qg + (size_t)(q0 + row) * FUSED_OUT + c2 * 2);
            float2 f = __half22float2(qv);
            *(__half2*)(smem + row * FQ_ROWB + c2 * 4) =
                __floats2half2_rn(f.x * scale, f.y * scale);
        }
    }

    // ---- stage loader (K block + V block, 64 seq-rows x 256B each) ----
    auto load_stage = [&](int buf, int j) {
        const uint32_t kb = kbase0 + buf * FSTAGE;
        const uint32_t vb = kb + FK_BYTES;
        const int kp0 = j * 64;
        #pragma unroll
        for (int i = 0; i < 4; i++) {
            int idx = tid + 256 * i;
            int row = idx >> 4, seg = idx & 15;
            CP_ASYNC16(kb + (uint32_t)(row * FQ_ROWB + seg * 16),
                       Kg + (size_t)(kp0 + row) * FUSED_OUT + seg * 8);
        }
        #pragma unroll
        for (int i = 0; i < 4; i++) {
            int idx = tid + 256 * i;
            int row = idx >> 4, seg = idx & 15;
            CP_ASYNC16(vb + (uint32_t)(row * FQ_ROWB + seg * 16),
                       Vg + (size_t)(kp0 + row) * FUSED_OUT + seg * 8);
        }
    };

    load_stage(0, 0);
    CP_COMMIT();
    __syncthreads();    // Q smem ready

    // ---- Q fragments (pre-scaled) ----
    uint32_t qf[8][4];
    {
        const uint32_t qoff = (uint32_t)((w * 16 + (lane & 15)) * FQ_ROWB + ((lane >> 4) << 4));
        #pragma unroll
        for (int kf = 0; kf < 8; kf++)
            LDSM4(qf[kf], sm_u + qoff + kf * 32);
    }

    // ---- state ----
    float oacc[16][4];
    #pragma unroll
    for (int i = 0; i < 16; i++)
        #pragma unroll
        for (int r = 0; r < 4; r++) oacc[i][r] = 0.f;
    float mrow0 = -INFINITY, mrow1 = -INFINITY;
    float lrow0 = 0.f, lrow1 = 0.f;

    const uint32_t kfrag_off = (uint32_t)(((lane & 7) + ((lane >> 4) << 3)) * FQ_ROWB +
                                          (((lane >> 3) & 1) << 4));
    const uint32_t vfrag_off = (uint32_t)((lane & 15) * FQ_ROWB + ((lane >> 4) << 4));

    for (int j = 0; j <= jmax; j++) {
        int buf = j & 1;
        if (j < jmax) { load_stage(buf ^ 1, j + 1); CP_COMMIT(); }
        if (j < jmax) { CP_WAIT1(); } else { CP_WAIT0(); }
        __syncthreads();

        const uint32_t kb = kbase0 + buf * FSTAGE;
        const uint32_t vb = kb + FK_BYTES;

        // ---- S = Q K^T (16 rows x 64 cols per warp) ----
        float sacc[8][4];
        #pragma unroll
        for (int nj = 0; nj < 8; nj++)
            #pragma unroll
            for (int r = 0; r < 4; r++) sacc[nj][r] = 0.f;
        #pragma unroll
        for (int njp = 0; njp < 4; njp++) {
            #pragma unroll
            for (int kf = 0; kf < 8; kf++) {
                uint32_t bf[4];
                LDSM4(bf, kb + kfrag_off + njp * (16 * FQ_ROWB) + kf * 32);
                mma16816(sacc[2 * njp + 0], qf[kf], &bf[0]);
                mma16816(sacc[2 * njp + 1], qf[kf], &bf[2]);
            }
        }

        // ---- causal mask: last two k-blocks overlap the diagonal band ----
        if (j >= jmax - 1) {
            int r0 = q0 + w * 16 + (lane >> 2);
            int cb = j * 64 + (lane & 3) * 2;
            #pragma unroll
            for (int nj = 0; nj < 8; nj++) {
                int c = cb + nj * 8;
                if (c > r0)     sacc[nj][0] = -1e30f;
                if (c + 1 > r0) sacc[nj][1] = -1e30f;
                if (c > r0 + 8)     sacc[nj][2] = -1e30f;
                if (c + 1 > r0 + 8) sacc[nj][3] = -1e30f;
            }
        }

        // ---- online softmax (rows within warp; reduce over lane&3) ----
        float bm0 = sacc[0][0], bm1 = sacc[0][2];
        #pragma unroll
        for (int nj = 0; nj < 8; nj++) {
            bm0 = fmaxf(bm0, fmaxf(sacc[nj][0], sacc[nj][1]));
            bm1 = fmaxf(bm1, fmaxf(sacc[nj][2], sacc[nj][3]));
        }
        #pragma unroll
        for (int off = 1; off <= 2; off <<= 1) {
            bm0 = fmaxf(bm0, __shfl_xor_sync(0xffffffffu, bm0, off));
            bm1 = fmaxf(bm1, __shfl_xor_sync(0xffffffffu, bm1, off));
        }
        float mnew0 = fmaxf(mrow0, bm0);
        float mnew1 = fmaxf(mrow1, bm1);
        float alpha0 = __expf(mrow0 - mnew0);
        float alpha1 = __expf(mrow1 - mnew1);
        mrow0 = mnew0; mrow1 = mnew1;

        uint32_t paf[4][4];
        float s0 = 0.f, s1 = 0.f;
        #pragma unroll
        for (int njp = 0; njp < 4; njp++) {
            float p00 = __expf(sacc[2 * njp + 0][0] - mnew0);
            float p01 = __expf(sacc[2 * njp + 0][1] - mnew0);
            float p02 = __expf(sacc[2 * njp + 0][2] - mnew1);
            float p03 = __expf(sacc[2 * njp + 0][3] - mnew1);
            float p10 = __expf(sacc[2 * njp + 1][0] - mnew0);
            float p11 = __expf(sacc[2 * njp + 1][1] - mnew0);
            float p12 = __expf(sacc[2 * njp + 1][2] - mnew1);
            float p13 = __expf(sacc[2 * njp + 1][3] - mnew1);
            s0 += p00 + p01 + p10 + p11;
            s1 += p02 + p03 + p12 + p13;
            paf[njp][0] = h2_u32(__floats2half2_rn(p00, p01));
            paf[njp][1] = h2_u32(__floats2half2_rn(p02, p03));
            paf[njp][2] = h2_u32(__floats2half2_rn(p10, p11));
            paf[njp][3] = h2_u32(__floats2half2_rn(p12, p13));
        }
        #pragma unroll
        for (int off = 1; off <= 2; off <<= 1) {
            s0 += __shfl_xor_sync(0xffffffffu, s0, off);
            s1 += __shfl_xor_sync(0xffffffffu, s1, off);
        }
        lrow0 = lrow0 * alpha0 + s0;
        lrow1 = lrow1 * alpha1 + s1;

        // ---- rescale O, then O += P V (trans-ldmatrix from [seq][dh]) ----
        #pragma unroll
        for (int i = 0; i < 16; i++) {
            oacc[i][0] *= alpha0; oacc[i][1] *= alpha0;
            oacc[i][2] *= alpha1; oacc[i][3] *= alpha1;
        }
        #pragma unroll
        for (int njp2 = 0; njp2 < 8; njp2++) {
            #pragma unroll
            for (int kf2 = 0; kf2 < 4; kf2++) {
                uint32_t bf[4];
                LDSM4T(bf, vb + vfrag_off + njp2 * 32 + kf2 * (16 * FQ_ROWB));
                mma16816(oacc[2 * njp2 + 0], paf[kf2], &bf[0]);
                mma16816(oacc[2 * njp2 + 1], paf[kf2], &bf[2]);
            }
        }
        __syncthreads();   // all warps done with this buffer before overwrite
    }

    // ---- write O ----
    float inv0 = 1.0f / lrow0;
    float inv1 = 1.0f / lrow1;
    int r0 = q0 + w * 16 + (lane >> 2);
    int cb = h * DH + (lane & 3) * 2;
    #pragma unroll
    for (int njo = 0; njo < 16; njo++) {
        int col = cb + njo * 8;
        *(__half2*)(g_cath + (size_t)r0 * CAT_K + col) =
            __floats2half2_rn(oacc[njo][0] * inv0, oacc[njo][1] * inv0);
        *(__half2*)(g_cath + (size_t)(r0 + 8) * CAT_K + col) =
            __floats2half2_rn(oacc[njo][2] * inv1, oacc[njo][3] * inv1);
    }
}

// --------------------------- SwiGLU activation ------------------------------
// proj half -> cat half cols [2048, 10240); uint4 (8 halves) per thread.
__global__ __launch_bounds__(256) void ff_act_kernel(void) {
    int row = blockIdx.y;
    int j8 = blockIdx.x * 256 + threadIdx.x;     // 8-half chunk index 0..1023
    const __half* prow = g_projh + (size_t)row * FUSED_OUT;
    uint4 xv = *(const uint4*)(prow + FF_BASE + j8 * 8);
    uint4 gv = *(const uint4*)(prow + GATE_BASE + j8 * 8);
    const uint32_t* xp = (const uint32_t*)&xv;
    const uint32_t* gp = (const uint32_t*)&gv;
    uint4 ov;
    uint32_t* op = (uint32_t*)&ov;
    #pragma unroll
    for (int k = 0; k < 4; k++) {
        union { uint32_t u; __half2 h; } xu, gu;
        xu.u = xp[k]; gu.u = gp[k];
        float2 xf = __half22float2(xu.h);
        float2 gf = __half22float2(gu.h);
        float o0 = xf.x * (gf.x / (1.0f + __expf(-gf.x)));
        float o1 = xf.y * (gf.y / (1.0f + __expf(-gf.y)));
        op[k] = h2_u32(__floats2half2_rn(o0, o1));
    }
    *(uint4*)(g_cath + (size_t)row * CAT_K + ATTN_INNER + j8 * 8) = ov;
}

// ------------------------------- launch -------------------------------------
extern "C" void kernel_launch(void* const* d_in, const int* in_sizes, int n_in,
                              void* d_out, int out_size) {
    const float* x          = (const float*)d_in[0];
    const float* gamma      = (const float*)d_in[1];
    const float* w_fused    = (const float*)d_in[2];
    const float* w_attn_out = (const float*)d_in[3];
    const float* w_ff_out   = (const float*)d_in[4];
    float* out = (float*)d_out;

    __half *p_xnh, *p_projh, *p_cath, *p_wfh, *p_wcath;
    cudaGetSymbolAddress((void**)&p_xnh, g_xnh);
    cudaGetSymbolAddress((void**)&p_projh, g_projh);
    cudaGetSymbolAddress((void**)&p_cath, g_cath);
    cudaGetSymbolAddress((void**)&p_wfh, g_wfh);
    cudaGetSymbolAddress((void**)&p_wcath, g_wcath);

    const int SMEM_DYN = NSTG * STAGE;   // 217088 B
    cudaFuncSetAttribute((const void*)mma_gemm<true>,
                         cudaFuncAttributeMaxDynamicSharedMemorySize, SMEM_DYN);
    cudaFuncSetAttribute((const void*)mma_gemm<false>,
                         cudaFuncAttributeMaxDynamicSharedMemorySize, SMEM_DYN);
    cudaFuncSetAttribute((const void*)flash_attn,
                         cudaFuncAttributeMaxDynamicSharedMemorySize, FSMEM);

    // 0. weight fp32->fp16 streaming converts, single launch (layout preserved)
    wconv3_kernel<<<dim3(1024, 3), 256>>>(
        w_fused, p_wfh, (size_t)DIM * FUSED_OUT,
        w_attn_out, p_wcath, (size_t)ATTN_INNER * DIM,
        w_ff_out, p_wcath + (size_t)ATTN_INNER * DIM, (size_t)FF_INNER * DIM);

    // 1. LayerNorm -> xn half
    ln_kernel<<<NSEQ, 256>>>(x, gamma);

    // 2. proj = xn @ wf  -> proj half   (wf [2048][18688])
    mma_gemm<true>
        <<<dim3(NSEQ / 256, FUSED_OUT / 128, 1), 256, SMEM_DYN>>>(
        p_xnh, DIM, p_wfh, FUSED_OUT, p_projh, FUSED_OUT, DIM);

    // 3-5. fused flash attention -> cat cols [0,2048)
    flash_attn<<<dim3(NSEQ / 128, HEADS), 256, FSMEM>>>();

    // 6. SwiGLU -> cat cols [2048, 10240)
    ff_act_kernel<<<dim3(FF_INNER / 2048, NSEQ), 256>>>();

    // 7. out = cat @ wcat  (fp32 out; wcat [10240][2048])
    mma_gemm<false>
        <<<dim3(NSEQ / 256, DIM / 128, 1), 256, SMEM_DYN>>>(
        p_cath, CAT_K, p_wcath, DIM, out, DIM, CAT_K);
}